// round 8
// baseline (speedup 1.0000x reference)
#include <cuda_runtime.h>

#define F_IN  14
#define HEADS 8
#define DIM   8
#define F1    64          // HEADS*DIM
#define NEG   0.2f
#define MAXN  100000
#define MAXE  1600000
#define TILE  1024
#define MAXT  ((MAXN + TILE - 1) / TILE)

// ------------------------- scratch (device globals; no allocs) -------------
__device__ float g_h1  [MAXN * F1];     // layer1 linear output [N,64]
__device__ float g_hL2 [MAXN * F1];     // layer1 final output (ELU'd) = layer2 input
__device__ float g_as1 [MAXN * HEADS];
__device__ float g_ad1 [MAXN * HEADS];
__device__ float g_h2  [MAXN * DIM];    // layer2 linear output [N,8]
__device__ float g_as2 [MAXN];
__device__ float g_ad2 [MAXN];
__device__ int   g_src [MAXE];
__device__ int   g_dst [MAXE];
__device__ int   g_ssrc[MAXE];          // src ids sorted by dst (CSR col idx)
__device__ int   g_cnt [MAXN];          // in-degree histogram
__device__ int   g_off [MAXN + 1];      // CSR row offsets
__device__ int   g_cur [MAXN];          // scatter cursors
__device__ int   g_bsum[MAXT];          // per-tile sums
__device__ int   g_bpre[MAXT];          // per-tile exclusive prefixes
__device__ int   g_is64;

// ------------------------- helpers ----------------------------------------
__device__ __forceinline__ float lrelu(float x) { return x > 0.f ? x : NEG * x; }

// ------------------------- edge dtype detect -------------------------------
__global__ void k_detect(const unsigned long long* p) {
    if (threadIdx.x == 0) {
        int is64 = 1;
        for (int i = 0; i < 64; i++)
            if (p[i] >> 32) { is64 = 0; break; }
        g_is64 = is64;
    }
}

__global__ void k_zero(int n) {
    int i = blockIdx.x * blockDim.x + threadIdx.x;
    if (i < n) g_cnt[i] = 0;
}

// convert indices to int32 + build dst histogram
__global__ void k_convert(const void* ei, int e) {
    int i = blockIdx.x * blockDim.x + threadIdx.x;
    if (i >= e) return;
    int s, d;
    if (g_is64) {
        const long long* p = (const long long*)ei;
        s = (int)p[i]; d = (int)p[e + i];
    } else {
        const int* p = (const int*)ei;
        s = p[i]; d = p[e + i];
    }
    g_src[i] = s;
    g_dst[i] = d;
    atomicAdd(&g_cnt[d], 1);
}

// ---- hierarchical scan: tile sums -> tiny scan -> per-tile offsets --------
__global__ void __launch_bounds__(256) k_tilesum(int n) {
    __shared__ int sw[8];
    int base = blockIdx.x * TILE;
    int t = threadIdx.x;
    int s = 0;
#pragma unroll
    for (int k = 0; k < 4; k++) {
        int i = base + t * 4 + k;
        if (i < n) s += g_cnt[i];
    }
#pragma unroll
    for (int m = 16; m; m >>= 1) s += __shfl_xor_sync(0xffffffffu, s, m);
    if ((t & 31) == 0) sw[t >> 5] = s;
    __syncthreads();
    if (t == 0) {
        int tot = 0;
#pragma unroll
        for (int w = 0; w < 8; w++) tot += sw[w];
        g_bsum[blockIdx.x] = tot;
    }
}

__global__ void __launch_bounds__(128) k_scanb(int ntiles, int n, int e) {
    __shared__ int sp[128];
    int t = threadIdx.x;
    int v = (t < ntiles) ? g_bsum[t] : 0;
    sp[t] = v;
    __syncthreads();
#pragma unroll
    for (int off = 1; off < 128; off <<= 1) {
        int u = (t >= off) ? sp[t - off] : 0;
        __syncthreads();
        sp[t] += u;
        __syncthreads();
    }
    if (t < ntiles) g_bpre[t] = sp[t] - v;     // exclusive prefix
    if (t == 0) g_off[n] = e;
}

__global__ void __launch_bounds__(256) k_offsets(int n) {
    __shared__ int sp[256];
    int base = blockIdx.x * TILE;
    int t = threadIdx.x;
    int v[4]; int s = 0;
#pragma unroll
    for (int k = 0; k < 4; k++) {
        int i = base + t * 4 + k;
        v[k] = (i < n) ? g_cnt[i] : 0;
        s += v[k];
    }
    sp[t] = s;
    __syncthreads();
#pragma unroll
    for (int off = 1; off < 256; off <<= 1) {
        int u = (t >= off) ? sp[t - off] : 0;
        __syncthreads();
        sp[t] += u;
        __syncthreads();
    }
    int run = g_bpre[blockIdx.x] + sp[t] - s;  // exclusive within block + tile prefix
#pragma unroll
    for (int k = 0; k < 4; k++) {
        int i = base + t * 4 + k;
        if (i < n) { g_off[i] = run; g_cur[i] = run; run += v[k]; }
    }
}

__global__ void k_scatter(int e) {
    int i = blockIdx.x * blockDim.x + threadIdx.x;
    if (i >= e) return;
    int d = g_dst[i];
    int pos = atomicAdd(&g_cur[d], 1);
    g_ssrc[pos] = g_src[i];
}

// ------------------------- layer 1: fused gemm + logits --------------------
__global__ void __launch_bounds__(256) k_l1(const float* __restrict__ x,
                                            const float* __restrict__ W1,
                                            const float* __restrict__ asrc,
                                            const float* __restrict__ adst, int n) {
    __shared__ float sW[F_IN * F1];
    __shared__ float sS[F1], sD[F1];
    int tid = threadIdx.x;
    for (int i = tid; i < F_IN * F1; i += 256) sW[i] = W1[i];
    if (tid < F1) { sS[tid] = asrc[tid]; sD[tid] = adst[tid]; }
    __syncthreads();

    int node = blockIdx.x * 4 + (tid >> 6);
    int c = tid & 63;
    if (node >= n) return;

    const float* xr = x + node * F_IN;
    float acc = 0.f;
#pragma unroll
    for (int k = 0; k < F_IN; k++) acc += xr[k] * sW[k * F1 + c];
    g_h1[node * F1 + c] = acc;

    float as = acc * sS[c], ad = acc * sD[c];
#pragma unroll
    for (int m = 1; m < 8; m <<= 1) {
        as += __shfl_xor_sync(0xffffffffu, as, m, 8);
        ad += __shfl_xor_sync(0xffffffffu, ad, m, 8);
    }
    if ((c & 7) == 0) {
        int j = node * HEADS + (c >> 3);
        g_as1[j] = as;
        g_ad1[j] = ad;
    }
}

// ------------------------- layer 1: warp-per-node gather + normalize+ELU ---
// 32 lanes = 4 edge-slots x 8 heads. Slots stride the adjacency list by 4;
// cross-slot reduction via 2 shfl_xor rounds at the end.
__global__ void __launch_bounds__(256) k_gather1(const float* __restrict__ b1, int n) {
    int tid  = threadIdx.x;
    int node = (blockIdx.x * 256 + tid) >> 5;
    if (node >= n) return;                 // warp-uniform
    int lane = tid & 31;
    int es = lane >> 3, h = lane & 7;

    int beg = g_off[node], end = g_off[node + 1];
    float ad = g_ad1[node * 8 + h];

    float4 acc0 = make_float4(0.f,0.f,0.f,0.f);
    float4 acc1 = make_float4(0.f,0.f,0.f,0.f);
    float ws = 0.f;

    if (es == 0) {                          // self-loop handled by slot 0
        float wl = __expf(lrelu(g_as1[node * 8 + h] + ad));
        float4 a0 = *(const float4*)(g_h1 + node * F1 + h * 8);
        float4 a1 = *(const float4*)(g_h1 + node * F1 + h * 8 + 4);
        acc0 = make_float4(a0.x*wl, a0.y*wl, a0.z*wl, a0.w*wl);
        acc1 = make_float4(a1.x*wl, a1.y*wl, a1.z*wl, a1.w*wl);
        ws = wl;
    }

    for (int j = beg + es; j < end; j += 4) {
        int s = g_ssrc[j];
        float w = __expf(lrelu(g_as1[s * 8 + h] + ad));
        float4 v0 = *(const float4*)(g_h1 + s * F1 + h * 8);
        float4 v1 = *(const float4*)(g_h1 + s * F1 + h * 8 + 4);
        acc0.x += v0.x * w; acc0.y += v0.y * w; acc0.z += v0.z * w; acc0.w += v0.w * w;
        acc1.x += v1.x * w; acc1.y += v1.y * w; acc1.z += v1.z * w; acc1.w += v1.w * w;
        ws += w;
    }

    // reduce the 4 edge-slots (lanes differing in bits 3,4)
#pragma unroll
    for (int m = 8; m <= 16; m <<= 1) {
        acc0.x += __shfl_xor_sync(0xffffffffu, acc0.x, m);
        acc0.y += __shfl_xor_sync(0xffffffffu, acc0.y, m);
        acc0.z += __shfl_xor_sync(0xffffffffu, acc0.z, m);
        acc0.w += __shfl_xor_sync(0xffffffffu, acc0.w, m);
        acc1.x += __shfl_xor_sync(0xffffffffu, acc1.x, m);
        acc1.y += __shfl_xor_sync(0xffffffffu, acc1.y, m);
        acc1.z += __shfl_xor_sync(0xffffffffu, acc1.z, m);
        acc1.w += __shfl_xor_sync(0xffffffffu, acc1.w, m);
        ws     += __shfl_xor_sync(0xffffffffu, ws, m);
    }

    if (es == 0) {
        float r = __fdividef(1.f, ws);
        float4 bb0 = *(const float4*)(b1 + h * 8);
        float4 bb1 = *(const float4*)(b1 + h * 8 + 4);
        float4 o0, o1;
        o0.x = acc0.x * r + bb0.x; o0.x = o0.x > 0.f ? o0.x : expm1f(o0.x);
        o0.y = acc0.y * r + bb0.y; o0.y = o0.y > 0.f ? o0.y : expm1f(o0.y);
        o0.z = acc0.z * r + bb0.z; o0.z = o0.z > 0.f ? o0.z : expm1f(o0.z);
        o0.w = acc0.w * r + bb0.w; o0.w = o0.w > 0.f ? o0.w : expm1f(o0.w);
        o1.x = acc1.x * r + bb1.x; o1.x = o1.x > 0.f ? o1.x : expm1f(o1.x);
        o1.y = acc1.y * r + bb1.y; o1.y = o1.y > 0.f ? o1.y : expm1f(o1.y);
        o1.z = acc1.z * r + bb1.z; o1.z = o1.z > 0.f ? o1.z : expm1f(o1.z);
        o1.w = acc1.w * r + bb1.w; o1.w = o1.w > 0.f ? o1.w : expm1f(o1.w);
        *(float4*)(g_hL2 + node * F1 + h * 8)     = o0;
        *(float4*)(g_hL2 + node * F1 + h * 8 + 4) = o1;
    }
}

// ------------------------- layer 2: gemm + logits ---------------------------
__global__ void __launch_bounds__(256) k_l2(const float* __restrict__ W2,
                                            const float* __restrict__ asrc,
                                            const float* __restrict__ adst, int n) {
    __shared__ float sW[F1 * DIM], sS[DIM], sD[DIM];
    int tid = threadIdx.x;
    for (int i = tid; i < F1 * DIM; i += 256) sW[i] = W2[i];
    if (tid < DIM) { sS[tid] = asrc[tid]; sD[tid] = adst[tid]; }
    __syncthreads();

    int nidx = blockIdx.x * blockDim.x + tid;
    if (nidx >= n) return;

    float acc[DIM] = {0.f,0.f,0.f,0.f,0.f,0.f,0.f,0.f};
    const float* row = g_hL2 + nidx * F1;
#pragma unroll
    for (int k = 0; k < F1; k += 4) {
        float4 t = *(const float4*)(row + k);
#pragma unroll
        for (int c = 0; c < DIM; c++)
            acc[c] += t.x * sW[k * 8 + c] + t.y * sW[(k + 1) * 8 + c]
                    + t.z * sW[(k + 2) * 8 + c] + t.w * sW[(k + 3) * 8 + c];
    }
    float as = 0.f, ad = 0.f;
#pragma unroll
    for (int c = 0; c < DIM; c++) {
        as += acc[c] * sS[c];
        ad += acc[c] * sD[c];
        g_h2[nidx * DIM + c] = acc[c];
    }
    g_as2[nidx] = as;
    g_ad2[nidx] = ad;
}

// ------------------------- layer 2: warp-per-node gather + finalize --------
// 32 lanes = 4 edge-slots x 8 output cols.
__global__ void __launch_bounds__(256) k_gather2(const float* __restrict__ b2,
                                                 int n, float* __restrict__ out) {
    int tid  = threadIdx.x;
    int node = (blockIdx.x * 256 + tid) >> 5;
    if (node >= n) return;
    int lane = tid & 31;
    int es = lane >> 3, c = lane & 7;

    int beg = g_off[node], end = g_off[node + 1];
    float ad = g_ad2[node];

    float acc = 0.f, ws = 0.f;
    if (es == 0) {
        float wl = __expf(lrelu(g_as2[node] + ad));
        acc = g_h2[node * DIM + c] * wl;
        ws = wl;
    }

    for (int j = beg + es; j < end; j += 4) {
        int s = g_ssrc[j];
        float w = __expf(lrelu(g_as2[s] + ad));
        acc += w * g_h2[s * DIM + c];
        ws += w;
    }

#pragma unroll
    for (int m = 8; m <= 16; m <<= 1) {
        acc += __shfl_xor_sync(0xffffffffu, acc, m);
        ws  += __shfl_xor_sync(0xffffffffu, ws, m);
    }

    if (es == 0)
        out[node * DIM + c] = acc * __fdividef(1.f, ws) + __ldg(&b2[c]);
}

// ------------------------- launch -----------------------------------------
extern "C" void kernel_launch(void* const* d_in, const int* in_sizes, int n_in,
                              void* d_out, int out_size) {
    const float* x   = (const float*)d_in[0];
    const void*  ei  = d_in[1];
    const float* W1  = (const float*)d_in[2];
    const float* as1 = (const float*)d_in[3];
    const float* ad1 = (const float*)d_in[4];
    const float* b1  = (const float*)d_in[5];
    const float* W2  = (const float*)d_in[6];
    const float* as2 = (const float*)d_in[7];
    const float* ad2 = (const float*)d_in[8];
    const float* b2  = (const float*)d_in[9];
    float* out = (float*)d_out;

    int n = in_sizes[0] / F_IN;
    int e = in_sizes[1] / 2;
    const int B = 256;
    auto g = [&](long long t) { return (unsigned)((t + B - 1) / B); };
    int ntiles = (n + TILE - 1) / TILE;
    int gw = (n + 7) / 8;                 // warp-per-node grids

    // CSR build
    k_detect  <<<1, 32>>>((const unsigned long long*)ei);
    k_zero    <<<g(n), B>>>(n);
    k_convert <<<g(e), B>>>(ei, e);
    k_tilesum <<<ntiles, B>>>(n);
    k_scanb   <<<1, 128>>>(ntiles, n, e);
    k_offsets <<<ntiles, B>>>(n);
    k_scatter <<<g(e), B>>>(e);

    // layer 1
    k_l1      <<<(n + 3) / 4, B>>>(x, W1, as1, ad1, n);
    k_gather1 <<<gw, B>>>(b1, n);

    // layer 2
    k_l2      <<<g(n), B>>>(W2, as2, ad2, n);
    k_gather2 <<<gw, B>>>(b2, n, out);
}

// round 9
// speedup vs baseline: 1.1491x; 1.1491x over previous
#include <cuda_runtime.h>

#define F_IN  14
#define HEADS 8
#define DIM   8
#define F1    64          // HEADS*DIM
#define NEG   0.2f
#define MAXN  100000
#define MAXE  1600000
#define TILE  1024
#define MAXT  ((MAXN + TILE - 1) / TILE)

// ------------------------- scratch (device globals; no allocs) -------------
__device__ float g_h1  [MAXN * F1];     // layer1 linear output [N,64]
__device__ float g_hL2 [MAXN * F1];     // layer1 final output (ELU'd) = layer2 input
__device__ float g_as1 [MAXN * HEADS];
__device__ float g_ad1 [MAXN * HEADS];
__device__ float g_h2  [MAXN * DIM];    // layer2 linear output [N,8]
__device__ float g_as2 [MAXN];
__device__ float g_ad2 [MAXN];
__device__ int   g_ssrc[MAXE];          // src ids sorted by dst (CSR col idx)
__device__ int   g_cnt [MAXN];          // in-degree histogram
__device__ int   g_off [MAXN + 1];      // CSR row offsets
__device__ int   g_cur [MAXN];          // scatter cursors
__device__ int   g_bsum[MAXT];          // per-tile sums
__device__ int   g_bpre[MAXT];          // per-tile exclusive prefixes
__device__ int   g_is64;

// ------------------------- helpers ----------------------------------------
__device__ __forceinline__ float lrelu(float x) { return x > 0.f ? x : NEG * x; }

// ------------------------- edge dtype detect -------------------------------
__global__ void k_detect(const unsigned long long* p) {
    if (threadIdx.x == 0) {
        int is64 = 1;
        for (int i = 0; i < 64; i++)
            if (p[i] >> 32) { is64 = 0; break; }
        g_is64 = is64;
    }
}

__global__ void k_zero(int n) {
    int i = blockIdx.x * blockDim.x + threadIdx.x;
    if (i < n) g_cnt[i] = 0;
}

// dst histogram straight from the input edge tensor (no int32 staging)
__global__ void k_hist(const void* ei, int e) {
    int i = blockIdx.x * blockDim.x + threadIdx.x;
    if (i >= e) return;
    int d = g_is64 ? (int)((const long long*)ei)[e + i]
                   : ((const int*)ei)[e + i];
    atomicAdd(&g_cnt[d], 1);
}

// ---- hierarchical scan: tile sums -> tiny scan -> per-tile offsets --------
__global__ void __launch_bounds__(256) k_tilesum(int n) {
    __shared__ int sw[8];
    int base = blockIdx.x * TILE;
    int t = threadIdx.x;
    int s = 0;
#pragma unroll
    for (int k = 0; k < 4; k++) {
        int i = base + t * 4 + k;
        if (i < n) s += g_cnt[i];
    }
#pragma unroll
    for (int m = 16; m; m >>= 1) s += __shfl_xor_sync(0xffffffffu, s, m);
    if ((t & 31) == 0) sw[t >> 5] = s;
    __syncthreads();
    if (t == 0) {
        int tot = 0;
#pragma unroll
        for (int w = 0; w < 8; w++) tot += sw[w];
        g_bsum[blockIdx.x] = tot;
    }
}

__global__ void __launch_bounds__(128) k_scanb(int ntiles, int n, int e) {
    __shared__ int sp[128];
    int t = threadIdx.x;
    int v = (t < ntiles) ? g_bsum[t] : 0;
    sp[t] = v;
    __syncthreads();
#pragma unroll
    for (int off = 1; off < 128; off <<= 1) {
        int u = (t >= off) ? sp[t - off] : 0;
        __syncthreads();
        sp[t] += u;
        __syncthreads();
    }
    if (t < ntiles) g_bpre[t] = sp[t] - v;     // exclusive prefix
    if (t == 0) g_off[n] = e;
}

__global__ void __launch_bounds__(256) k_offsets(int n) {
    __shared__ int sp[256];
    int base = blockIdx.x * TILE;
    int t = threadIdx.x;
    int v[4]; int s = 0;
#pragma unroll
    for (int k = 0; k < 4; k++) {
        int i = base + t * 4 + k;
        v[k] = (i < n) ? g_cnt[i] : 0;
        s += v[k];
    }
    sp[t] = s;
    __syncthreads();
#pragma unroll
    for (int off = 1; off < 256; off <<= 1) {
        int u = (t >= off) ? sp[t - off] : 0;
        __syncthreads();
        sp[t] += u;
        __syncthreads();
    }
    int run = g_bpre[blockIdx.x] + sp[t] - s;  // exclusive within block + tile prefix
#pragma unroll
    for (int k = 0; k < 4; k++) {
        int i = base + t * 4 + k;
        if (i < n) { g_off[i] = run; g_cur[i] = run; run += v[k]; }
    }
}

// scatter straight from the input edge tensor
__global__ void k_scatter(const void* ei, int e) {
    int i = blockIdx.x * blockDim.x + threadIdx.x;
    if (i >= e) return;
    int s, d;
    if (g_is64) {
        const long long* p = (const long long*)ei;
        s = (int)p[i]; d = (int)p[e + i];
    } else {
        const int* p = (const int*)ei;
        s = p[i]; d = p[e + i];
    }
    int pos = atomicAdd(&g_cur[d], 1);
    g_ssrc[pos] = s;
}

// ------------------------- layer 1: fused gemm + logits --------------------
__global__ void __launch_bounds__(256) k_l1(const float* __restrict__ x,
                                            const float* __restrict__ W1,
                                            const float* __restrict__ asrc,
                                            const float* __restrict__ adst, int n) {
    __shared__ float sW[F_IN * F1];
    __shared__ float sS[F1], sD[F1];
    int tid = threadIdx.x;
    for (int i = tid; i < F_IN * F1; i += 256) sW[i] = W1[i];
    if (tid < F1) { sS[tid] = asrc[tid]; sD[tid] = adst[tid]; }
    __syncthreads();

    int node = blockIdx.x * 4 + (tid >> 6);
    int c = tid & 63;
    if (node >= n) return;

    const float* xr = x + node * F_IN;
    float acc = 0.f;
#pragma unroll
    for (int k = 0; k < F_IN; k++) acc += xr[k] * sW[k * F1 + c];
    g_h1[node * F1 + c] = acc;

    float as = acc * sS[c], ad = acc * sD[c];
#pragma unroll
    for (int m = 1; m < 8; m <<= 1) {
        as += __shfl_xor_sync(0xffffffffu, as, m, 8);
        ad += __shfl_xor_sync(0xffffffffu, ad, m, 8);
    }
    if ((c & 7) == 0) {
        int j = node * HEADS + (c >> 3);
        g_as1[j] = as;
        g_ad1[j] = ad;
    }
}

// ------------------------- layer 1: dst-centric gather + normalize+ELU -----
// 8 threads per node (R6 structure), 2-edge software pipelining for MLP.
__global__ void __launch_bounds__(256) k_gather1(const float* __restrict__ b1, int n) {
    int tid = threadIdx.x;
    int node = blockIdx.x * 32 + (tid >> 3);
    int h = tid & 7;
    if (node >= n) return;

    int beg = g_off[node], end = g_off[node + 1];
    float ad = g_ad1[node * 8 + h];

    // self-loop
    float wl = __expf(lrelu(g_as1[node * 8 + h] + ad));
    float4 a0 = *(const float4*)(g_h1 + node * F1 + h * 8);
    float4 a1 = *(const float4*)(g_h1 + node * F1 + h * 8 + 4);
    float4 acc0 = make_float4(a0.x*wl, a0.y*wl, a0.z*wl, a0.w*wl);
    float4 acc1 = make_float4(a1.x*wl, a1.y*wl, a1.z*wl, a1.w*wl);
    float ws = wl;

    int j = beg;
    for (; j + 1 < end; j += 2) {          // two independent edges in flight
        int s0 = g_ssrc[j], s1 = g_ssrc[j + 1];
        float e0 = g_as1[s0 * 8 + h], e1 = g_as1[s1 * 8 + h];
        float4 u0 = *(const float4*)(g_h1 + s0 * F1 + h * 8);
        float4 u1 = *(const float4*)(g_h1 + s0 * F1 + h * 8 + 4);
        float4 v0 = *(const float4*)(g_h1 + s1 * F1 + h * 8);
        float4 v1 = *(const float4*)(g_h1 + s1 * F1 + h * 8 + 4);
        float w0 = __expf(lrelu(e0 + ad));
        float w1 = __expf(lrelu(e1 + ad));
        acc0.x += u0.x * w0; acc0.y += u0.y * w0; acc0.z += u0.z * w0; acc0.w += u0.w * w0;
        acc1.x += u1.x * w0; acc1.y += u1.y * w0; acc1.z += u1.z * w0; acc1.w += u1.w * w0;
        acc0.x += v0.x * w1; acc0.y += v0.y * w1; acc0.z += v0.z * w1; acc0.w += v0.w * w1;
        acc1.x += v1.x * w1; acc1.y += v1.y * w1; acc1.z += v1.z * w1; acc1.w += v1.w * w1;
        ws += w0 + w1;
    }
    if (j < end) {
        int s = g_ssrc[j];
        float w = __expf(lrelu(g_as1[s * 8 + h] + ad));
        float4 v0 = *(const float4*)(g_h1 + s * F1 + h * 8);
        float4 v1 = *(const float4*)(g_h1 + s * F1 + h * 8 + 4);
        acc0.x += v0.x * w; acc0.y += v0.y * w; acc0.z += v0.z * w; acc0.w += v0.w * w;
        acc1.x += v1.x * w; acc1.y += v1.y * w; acc1.z += v1.z * w; acc1.w += v1.w * w;
        ws += w;
    }

    float r = __fdividef(1.f, ws);
    float4 bb0 = *(const float4*)(b1 + h * 8);
    float4 bb1 = *(const float4*)(b1 + h * 8 + 4);
    float4 o0, o1;
    o0.x = acc0.x * r + bb0.x; o0.x = o0.x > 0.f ? o0.x : expm1f(o0.x);
    o0.y = acc0.y * r + bb0.y; o0.y = o0.y > 0.f ? o0.y : expm1f(o0.y);
    o0.z = acc0.z * r + bb0.z; o0.z = o0.z > 0.f ? o0.z : expm1f(o0.z);
    o0.w = acc0.w * r + bb0.w; o0.w = o0.w > 0.f ? o0.w : expm1f(o0.w);
    o1.x = acc1.x * r + bb1.x; o1.x = o1.x > 0.f ? o1.x : expm1f(o1.x);
    o1.y = acc1.y * r + bb1.y; o1.y = o1.y > 0.f ? o1.y : expm1f(o1.y);
    o1.z = acc1.z * r + bb1.z; o1.z = o1.z > 0.f ? o1.z : expm1f(o1.z);
    o1.w = acc1.w * r + bb1.w; o1.w = o1.w > 0.f ? o1.w : expm1f(o1.w);
    *(float4*)(g_hL2 + node * F1 + h * 8)     = o0;
    *(float4*)(g_hL2 + node * F1 + h * 8 + 4) = o1;
}

// ------------------------- layer 2: gemm + logits ---------------------------
__global__ void __launch_bounds__(256) k_l2(const float* __restrict__ W2,
                                            const float* __restrict__ asrc,
                                            const float* __restrict__ adst, int n) {
    __shared__ float sW[F1 * DIM], sS[DIM], sD[DIM];
    int tid = threadIdx.x;
    for (int i = tid; i < F1 * DIM; i += 256) sW[i] = W2[i];
    if (tid < DIM) { sS[tid] = asrc[tid]; sD[tid] = adst[tid]; }
    __syncthreads();

    int nidx = blockIdx.x * blockDim.x + tid;
    if (nidx >= n) return;

    float acc[DIM] = {0.f,0.f,0.f,0.f,0.f,0.f,0.f,0.f};
    const float* row = g_hL2 + nidx * F1;
#pragma unroll
    for (int k = 0; k < F1; k += 4) {
        float4 t = *(const float4*)(row + k);
#pragma unroll
        for (int c = 0; c < DIM; c++)
            acc[c] += t.x * sW[k * 8 + c] + t.y * sW[(k + 1) * 8 + c]
                    + t.z * sW[(k + 2) * 8 + c] + t.w * sW[(k + 3) * 8 + c];
    }
    float as = 0.f, ad = 0.f;
#pragma unroll
    for (int c = 0; c < DIM; c++) {
        as += acc[c] * sS[c];
        ad += acc[c] * sD[c];
        g_h2[nidx * DIM + c] = acc[c];
    }
    g_as2[nidx] = as;
    g_ad2[nidx] = ad;
}

// ------------------------- layer 2: dst-centric gather + finalize ----------
// 8 threads per node, 4-edge pipelining (scalar loads).
__global__ void __launch_bounds__(256) k_gather2(const float* __restrict__ b2,
                                                 int n, float* __restrict__ out) {
    int tid = threadIdx.x;
    int node = blockIdx.x * 32 + (tid >> 3);
    int c = tid & 7;
    if (node >= n) return;

    int beg = g_off[node], end = g_off[node + 1];
    float ad = g_ad2[node];

    float wl = __expf(lrelu(g_as2[node] + ad));
    float acc = g_h2[node * DIM + c] * wl;
    float ws = wl;

    int j = beg;
    for (; j + 3 < end; j += 4) {
        int s0 = g_ssrc[j],     s1 = g_ssrc[j + 1];
        int s2 = g_ssrc[j + 2], s3 = g_ssrc[j + 3];
        float e0 = g_as2[s0], e1 = g_as2[s1], e2 = g_as2[s2], e3 = g_as2[s3];
        float f0 = g_h2[s0 * DIM + c], f1 = g_h2[s1 * DIM + c];
        float f2 = g_h2[s2 * DIM + c], f3 = g_h2[s3 * DIM + c];
        float w0 = __expf(lrelu(e0 + ad)), w1 = __expf(lrelu(e1 + ad));
        float w2 = __expf(lrelu(e2 + ad)), w3 = __expf(lrelu(e3 + ad));
        acc += w0 * f0 + w1 * f1 + w2 * f2 + w3 * f3;
        ws  += w0 + w1 + w2 + w3;
    }
    for (; j < end; j++) {
        int s = g_ssrc[j];
        float w = __expf(lrelu(g_as2[s] + ad));
        acc += w * g_h2[s * DIM + c];
        ws += w;
    }
    out[node * DIM + c] = acc * __fdividef(1.f, ws) + __ldg(&b2[c]);
}

// ------------------------- launch -----------------------------------------
extern "C" void kernel_launch(void* const* d_in, const int* in_sizes, int n_in,
                              void* d_out, int out_size) {
    const float* x   = (const float*)d_in[0];
    const void*  ei  = d_in[1];
    const float* W1  = (const float*)d_in[2];
    const float* as1 = (const float*)d_in[3];
    const float* ad1 = (const float*)d_in[4];
    const float* b1  = (const float*)d_in[5];
    const float* W2  = (const float*)d_in[6];
    const float* as2 = (const float*)d_in[7];
    const float* ad2 = (const float*)d_in[8];
    const float* b2  = (const float*)d_in[9];
    float* out = (float*)d_out;

    int n = in_sizes[0] / F_IN;
    int e = in_sizes[1] / 2;
    const int B = 256;
    auto g = [&](long long t) { return (unsigned)((t + B - 1) / B); };
    int ntiles = (n + TILE - 1) / TILE;

    // CSR build (no int32 staging of src/dst)
    k_detect  <<<1, 32>>>((const unsigned long long*)ei);
    k_zero    <<<g(n), B>>>(n);
    k_hist    <<<g(e), B>>>(ei, e);
    k_tilesum <<<ntiles, B>>>(n);
    k_scanb   <<<1, 128>>>(ntiles, n, e);
    k_offsets <<<ntiles, B>>>(n);
    k_scatter <<<g(e), B>>>(ei, e);

    // layer 1
    k_l1      <<<(n + 3) / 4, B>>>(x, W1, as1, ad1, n);
    k_gather1 <<<(n + 31) / 32, B>>>(b1, n);

    // layer 2
    k_l2      <<<g(n), B>>>(W2, as2, ad2, n);
    k_gather2 <<<(n + 31) / 32, B>>>(b2, n, out);
}

// round 10
// speedup vs baseline: 1.2510x; 1.0887x over previous
#include <cuda_runtime.h>
#include <cuda_fp16.h>

#define F_IN  14
#define HEADS 8
#define DIM   8
#define F1    64          // HEADS*DIM
#define NEG   0.2f
#define MAXN  100000
#define MAXE  1600000
#define TILE  1024
#define MAXT  ((MAXN + TILE - 1) / TILE)

// ------------------------- scratch (device globals; no allocs) -------------
__device__ __half g_h1h[MAXN * F1];     // layer1 linear output, fp16-packed [N,64]
__device__ float g_hL2 [MAXN * F1];     // layer1 final output (ELU'd) = layer2 input
__device__ float g_as1 [MAXN * HEADS];  // logits stay fp32 (computed pre-rounding)
__device__ float g_ad1 [MAXN * HEADS];
__device__ float g_h2  [MAXN * DIM];    // layer2 linear output [N,8]
__device__ float g_as2 [MAXN];
__device__ float g_ad2 [MAXN];
__device__ int   g_ssrc[MAXE];          // src ids sorted by dst (CSR col idx)
__device__ int   g_cnt [MAXN];          // in-degree histogram
__device__ int   g_off [MAXN + 1];      // CSR row offsets
__device__ int   g_cur [MAXN];          // scatter cursors
__device__ int   g_bsum[MAXT];          // per-tile sums
__device__ int   g_bpre[MAXT];          // per-tile exclusive prefixes
__device__ int   g_is64;

// ------------------------- helpers ----------------------------------------
__device__ __forceinline__ float lrelu(float x) { return x > 0.f ? x : NEG * x; }

// accumulate 8 fp16 features (one uint4) into two float4 accs, scaled by w
__device__ __forceinline__ void acc8h(const uint4 u, float w, float4& a0, float4& a1) {
    float2 p0 = __half22float2(*(const __half2*)&u.x);
    float2 p1 = __half22float2(*(const __half2*)&u.y);
    float2 p2 = __half22float2(*(const __half2*)&u.z);
    float2 p3 = __half22float2(*(const __half2*)&u.w);
    a0.x += p0.x * w; a0.y += p0.y * w; a0.z += p1.x * w; a0.w += p1.y * w;
    a1.x += p2.x * w; a1.y += p2.y * w; a1.z += p3.x * w; a1.w += p3.y * w;
}

// ------------------------- edge dtype detect -------------------------------
__global__ void k_detect(const unsigned long long* p) {
    if (threadIdx.x == 0) {
        int is64 = 1;
        for (int i = 0; i < 64; i++)
            if (p[i] >> 32) { is64 = 0; break; }
        g_is64 = is64;
    }
}

__global__ void k_zero(int n) {
    int i = blockIdx.x * blockDim.x + threadIdx.x;
    if (i < n) g_cnt[i] = 0;
}

// dst histogram straight from the input edge tensor
__global__ void k_hist(const void* ei, int e) {
    int i = blockIdx.x * blockDim.x + threadIdx.x;
    if (i >= e) return;
    int d = g_is64 ? (int)((const long long*)ei)[e + i]
                   : ((const int*)ei)[e + i];
    atomicAdd(&g_cnt[d], 1);
}

// ---- hierarchical scan: tile sums -> tiny scan -> per-tile offsets --------
__global__ void __launch_bounds__(256) k_tilesum(int n) {
    __shared__ int sw[8];
    int base = blockIdx.x * TILE;
    int t = threadIdx.x;
    int s = 0;
#pragma unroll
    for (int k = 0; k < 4; k++) {
        int i = base + t * 4 + k;
        if (i < n) s += g_cnt[i];
    }
#pragma unroll
    for (int m = 16; m; m >>= 1) s += __shfl_xor_sync(0xffffffffu, s, m);
    if ((t & 31) == 0) sw[t >> 5] = s;
    __syncthreads();
    if (t == 0) {
        int tot = 0;
#pragma unroll
        for (int w = 0; w < 8; w++) tot += sw[w];
        g_bsum[blockIdx.x] = tot;
    }
}

__global__ void __launch_bounds__(128) k_scanb(int ntiles, int n, int e) {
    __shared__ int sp[128];
    int t = threadIdx.x;
    int v = (t < ntiles) ? g_bsum[t] : 0;
    sp[t] = v;
    __syncthreads();
#pragma unroll
    for (int off = 1; off < 128; off <<= 1) {
        int u = (t >= off) ? sp[t - off] : 0;
        __syncthreads();
        sp[t] += u;
        __syncthreads();
    }
    if (t < ntiles) g_bpre[t] = sp[t] - v;     // exclusive prefix
    if (t == 0) g_off[n] = e;
}

__global__ void __launch_bounds__(256) k_offsets(int n) {
    __shared__ int sp[256];
    int base = blockIdx.x * TILE;
    int t = threadIdx.x;
    int v[4]; int s = 0;
#pragma unroll
    for (int k = 0; k < 4; k++) {
        int i = base + t * 4 + k;
        v[k] = (i < n) ? g_cnt[i] : 0;
        s += v[k];
    }
    sp[t] = s;
    __syncthreads();
#pragma unroll
    for (int off = 1; off < 256; off <<= 1) {
        int u = (t >= off) ? sp[t - off] : 0;
        __syncthreads();
        sp[t] += u;
        __syncthreads();
    }
    int run = g_bpre[blockIdx.x] + sp[t] - s;
#pragma unroll
    for (int k = 0; k < 4; k++) {
        int i = base + t * 4 + k;
        if (i < n) { g_off[i] = run; g_cur[i] = run; run += v[k]; }
    }
}

// scatter straight from the input edge tensor
__global__ void k_scatter(const void* ei, int e) {
    int i = blockIdx.x * blockDim.x + threadIdx.x;
    if (i >= e) return;
    int s, d;
    if (g_is64) {
        const long long* p = (const long long*)ei;
        s = (int)p[i]; d = (int)p[e + i];
    } else {
        const int* p = (const int*)ei;
        s = p[i]; d = p[e + i];
    }
    int pos = atomicAdd(&g_cur[d], 1);
    g_ssrc[pos] = s;
}

// ------------------------- layer 1: fused gemm + logits --------------------
// Logits from the fp32 accumulator; h1 stored fp16.
__global__ void __launch_bounds__(256) k_l1(const float* __restrict__ x,
                                            const float* __restrict__ W1,
                                            const float* __restrict__ asrc,
                                            const float* __restrict__ adst, int n) {
    __shared__ float sW[F_IN * F1];
    __shared__ float sS[F1], sD[F1];
    int tid = threadIdx.x;
    for (int i = tid; i < F_IN * F1; i += 256) sW[i] = W1[i];
    if (tid < F1) { sS[tid] = asrc[tid]; sD[tid] = adst[tid]; }
    __syncthreads();

    int node = blockIdx.x * 4 + (tid >> 6);
    int c = tid & 63;
    if (node >= n) return;

    const float* xr = x + node * F_IN;
    float acc = 0.f;
#pragma unroll
    for (int k = 0; k < F_IN; k++) acc += xr[k] * sW[k * F1 + c];
    g_h1h[node * F1 + c] = __float2half_rn(acc);

    float as = acc * sS[c], ad = acc * sD[c];
#pragma unroll
    for (int m = 1; m < 8; m <<= 1) {
        as += __shfl_xor_sync(0xffffffffu, as, m, 8);
        ad += __shfl_xor_sync(0xffffffffu, ad, m, 8);
    }
    if ((c & 7) == 0) {
        int j = node * HEADS + (c >> 3);
        g_as1[j] = as;
        g_ad1[j] = ad;
    }
}

// ------------------------- layer 1: dst-centric gather + normalize+ELU -----
// 8 threads per node; fp16 feature rows (one uint4 per edge); 2-edge pipeline.
__global__ void __launch_bounds__(256) k_gather1(const float* __restrict__ b1, int n) {
    int tid = threadIdx.x;
    int node = blockIdx.x * 32 + (tid >> 3);
    int h = tid & 7;
    if (node >= n) return;

    int beg = g_off[node], end = g_off[node + 1];
    float ad = g_ad1[node * 8 + h];

    float4 acc0 = make_float4(0.f, 0.f, 0.f, 0.f);
    float4 acc1 = make_float4(0.f, 0.f, 0.f, 0.f);

    // self-loop
    float wl = __expf(lrelu(g_as1[node * 8 + h] + ad));
    acc8h(*(const uint4*)(g_h1h + node * F1 + h * 8), wl, acc0, acc1);
    float ws = wl;

    int j = beg;
    for (; j + 1 < end; j += 2) {          // two independent edges in flight
        int s0 = g_ssrc[j], s1 = g_ssrc[j + 1];
        float e0 = g_as1[s0 * 8 + h], e1 = g_as1[s1 * 8 + h];
        uint4 u = *(const uint4*)(g_h1h + s0 * F1 + h * 8);
        uint4 v = *(const uint4*)(g_h1h + s1 * F1 + h * 8);
        float w0 = __expf(lrelu(e0 + ad));
        float w1 = __expf(lrelu(e1 + ad));
        acc8h(u, w0, acc0, acc1);
        acc8h(v, w1, acc0, acc1);
        ws += w0 + w1;
    }
    if (j < end) {
        int s = g_ssrc[j];
        float w = __expf(lrelu(g_as1[s * 8 + h] + ad));
        acc8h(*(const uint4*)(g_h1h + s * F1 + h * 8), w, acc0, acc1);
        ws += w;
    }

    float r = __fdividef(1.f, ws);
    float4 bb0 = *(const float4*)(b1 + h * 8);
    float4 bb1 = *(const float4*)(b1 + h * 8 + 4);
    float4 o0, o1;
    o0.x = acc0.x * r + bb0.x; o0.x = o0.x > 0.f ? o0.x : expm1f(o0.x);
    o0.y = acc0.y * r + bb0.y; o0.y = o0.y > 0.f ? o0.y : expm1f(o0.y);
    o0.z = acc0.z * r + bb0.z; o0.z = o0.z > 0.f ? o0.z : expm1f(o0.z);
    o0.w = acc0.w * r + bb0.w; o0.w = o0.w > 0.f ? o0.w : expm1f(o0.w);
    o1.x = acc1.x * r + bb1.x; o1.x = o1.x > 0.f ? o1.x : expm1f(o1.x);
    o1.y = acc1.y * r + bb1.y; o1.y = o1.y > 0.f ? o1.y : expm1f(o1.y);
    o1.z = acc1.z * r + bb1.z; o1.z = o1.z > 0.f ? o1.z : expm1f(o1.z);
    o1.w = acc1.w * r + bb1.w; o1.w = o1.w > 0.f ? o1.w : expm1f(o1.w);
    *(float4*)(g_hL2 + node * F1 + h * 8)     = o0;
    *(float4*)(g_hL2 + node * F1 + h * 8 + 4) = o1;
}

// ------------------------- layer 2: gemm + logits ---------------------------
__global__ void __launch_bounds__(256) k_l2(const float* __restrict__ W2,
                                            const float* __restrict__ asrc,
                                            const float* __restrict__ adst, int n) {
    __shared__ float sW[F1 * DIM], sS[DIM], sD[DIM];
    int tid = threadIdx.x;
    for (int i = tid; i < F1 * DIM; i += 256) sW[i] = W2[i];
    if (tid < DIM) { sS[tid] = asrc[tid]; sD[tid] = adst[tid]; }
    __syncthreads();

    int nidx = blockIdx.x * blockDim.x + tid;
    if (nidx >= n) return;

    float acc[DIM] = {0.f,0.f,0.f,0.f,0.f,0.f,0.f,0.f};
    const float* row = g_hL2 + nidx * F1;
#pragma unroll
    for (int k = 0; k < F1; k += 4) {
        float4 t = *(const float4*)(row + k);
#pragma unroll
        for (int c = 0; c < DIM; c++)
            acc[c] += t.x * sW[k * 8 + c] + t.y * sW[(k + 1) * 8 + c]
                    + t.z * sW[(k + 2) * 8 + c] + t.w * sW[(k + 3) * 8 + c];
    }
    float as = 0.f, ad = 0.f;
#pragma unroll
    for (int c = 0; c < DIM; c++) {
        as += acc[c] * sS[c];
        ad += acc[c] * sD[c];
        g_h2[nidx * DIM + c] = acc[c];
    }
    g_as2[nidx] = as;
    g_ad2[nidx] = ad;
}

// ------------------------- layer 2: dst-centric gather + finalize ----------
__global__ void __launch_bounds__(256) k_gather2(const float* __restrict__ b2,
                                                 int n, float* __restrict__ out) {
    int tid = threadIdx.x;
    int node = blockIdx.x * 32 + (tid >> 3);
    int c = tid & 7;
    if (node >= n) return;

    int beg = g_off[node], end = g_off[node + 1];
    float ad = g_ad2[node];

    float wl = __expf(lrelu(g_as2[node] + ad));
    float acc = g_h2[node * DIM + c] * wl;
    float ws = wl;

    int j = beg;
    for (; j + 3 < end; j += 4) {
        int s0 = g_ssrc[j],     s1 = g_ssrc[j + 1];
        int s2 = g_ssrc[j + 2], s3 = g_ssrc[j + 3];
        float e0 = g_as2[s0], e1 = g_as2[s1], e2 = g_as2[s2], e3 = g_as2[s3];
        float f0 = g_h2[s0 * DIM + c], f1 = g_h2[s1 * DIM + c];
        float f2 = g_h2[s2 * DIM + c], f3 = g_h2[s3 * DIM + c];
        float w0 = __expf(lrelu(e0 + ad)), w1 = __expf(lrelu(e1 + ad));
        float w2 = __expf(lrelu(e2 + ad)), w3 = __expf(lrelu(e3 + ad));
        acc += w0 * f0 + w1 * f1 + w2 * f2 + w3 * f3;
        ws  += w0 + w1 + w2 + w3;
    }
    for (; j < end; j++) {
        int s = g_ssrc[j];
        float w = __expf(lrelu(g_as2[s] + ad));
        acc += w * g_h2[s * DIM + c];
        ws += w;
    }
    out[node * DIM + c] = acc * __fdividef(1.f, ws) + __ldg(&b2[c]);
}

// ------------------------- launch -----------------------------------------
extern "C" void kernel_launch(void* const* d_in, const int* in_sizes, int n_in,
                              void* d_out, int out_size) {
    const float* x   = (const float*)d_in[0];
    const void*  ei  = d_in[1];
    const float* W1  = (const float*)d_in[2];
    const float* as1 = (const float*)d_in[3];
    const float* ad1 = (const float*)d_in[4];
    const float* b1  = (const float*)d_in[5];
    const float* W2  = (const float*)d_in[6];
    const float* as2 = (const float*)d_in[7];
    const float* ad2 = (const float*)d_in[8];
    const float* b2  = (const float*)d_in[9];
    float* out = (float*)d_out;

    int n = in_sizes[0] / F_IN;
    int e = in_sizes[1] / 2;
    const int B = 256;
    auto g = [&](long long t) { return (unsigned)((t + B - 1) / B); };
    int ntiles = (n + TILE - 1) / TILE;

    // CSR build
    k_detect  <<<1, 32>>>((const unsigned long long*)ei);
    k_zero    <<<g(n), B>>>(n);
    k_hist    <<<g(e), B>>>(ei, e);
    k_tilesum <<<ntiles, B>>>(n);
    k_scanb   <<<1, 128>>>(ntiles, n, e);
    k_offsets <<<ntiles, B>>>(n);
    k_scatter <<<g(e), B>>>(ei, e);

    // layer 1
    k_l1      <<<(n + 3) / 4, B>>>(x, W1, as1, ad1, n);
    k_gather1 <<<(n + 31) / 32, B>>>(b1, n);

    // layer 2
    k_l2      <<<g(n), B>>>(W2, as2, ad2, n);
    k_gather2 <<<(n + 31) / 32, B>>>(b2, n, out);
}